// round 6
// baseline (speedup 1.0000x reference)
#include <cuda_runtime.h>

// SplineLoss on GB300: reference samples the spline only at integer knot
// times (t = 0,10,...,1020) where dx == 0.0 exactly, so all moment terms
// vanish: loss == mean over s,b,d of (true[b,10s,d]-pred[b,10s,d])^2.
//
// R6: one float4-pair per thread, max single-wave parallelism.
//  - 824 blocks (103 sample times x 8) x 256 thr = 210944 threads
//    (~5.6 blocks/SM, ~1430 thr/SM, single wave, occ ~70%)
//  - 2 front-batched LDG.128 per thread -> one DRAM latency per warp
//  - deterministic fixed-point fused atomic tail (sum<<16 | count):
//    last block reads full sum from the returned old value. No fence,
//    no partials array.

#define T_ 1024
#define D4_ 16                   // 64 floats per row = 16 float4
#define S_ 103                   // sample times 0,10,...,1020
#define ROW_STRIDE4_ (T_ * D4_)  // float4 stride between batches
#define COUNT_ 843776.0          // 128 * 103 * 64
#define FIX_SCALE 16777216.0     // 2^24

constexpr int NBLK = 8 * S_;     // 824: 8 blocks per sample time
constexpr int NTHR = 256;        // 16 batches x 16 float4

__device__ unsigned long long g_acc = 0;   // [63:16] fixed sum, [15:0] count

__global__ __launch_bounds__(NTHR) void spline_mse_r6(
    const float* __restrict__ yt, const float* __restrict__ yp,
    float* __restrict__ out)
{
    const int s = blockIdx.x >> 3;             // 0..102
    const int q = blockIdx.x & 7;              // batch group [16q, 16q+16)
    const int d4   = threadIdx.x & (D4_ - 1);
    const int brel = threadIdx.x >> 4;         // 0..15

    const int addr = s * 10 * D4_ + (q * 16 + brel) * ROW_STRIDE4_ + d4;
    const float4 va = __ldg((const float4*)yt + addr);
    const float4 vb = __ldg((const float4*)yp + addr);

    float e0 = va.x - vb.x;
    float e1 = va.y - vb.y;
    float e2 = va.z - vb.z;
    float e3 = va.w - vb.w;
    float acc = e0 * e0;
    acc = fmaf(e1, e1, acc);
    acc = fmaf(e2, e2, acc);
    acc = fmaf(e3, e3, acc);

    // block reduce (fixed order -> deterministic)
    #pragma unroll
    for (int o = 16; o > 0; o >>= 1)
        acc += __shfl_down_sync(0xffffffffu, acc, o);

    __shared__ float sh[NTHR / 32];
    if ((threadIdx.x & 31) == 0) sh[threadIdx.x >> 5] = acc;
    __syncthreads();

    if (threadIdx.x >= 32) return;             // warp 0 only

    float v = (threadIdx.x < NTHR / 32) ? sh[threadIdx.x] : 0.0f;
    #pragma unroll
    for (int o = 4; o > 0; o >>= 1)            // 8 lanes carry data
        v += __shfl_down_sync(0xffffffffu, v, o);

    if (threadIdx.x != 0) return;

    // deterministic fixed-point accumulate + ticket, fused in one atomic
    unsigned long long fixed =
        __double2ull_rn((double)v * FIX_SCALE);        // v >= 0
    unsigned long long packed = (fixed << 16) | 1ull;
    unsigned long long old = atomicAdd(&g_acc, packed);

    if ((old & 0xFFFFull) == (unsigned long long)(NBLK - 1)) {
        unsigned long long total = (old >> 16) + fixed;
        out[0] = (float)((double)total / (FIX_SCALE * COUNT_));
        g_acc = 0ull;                          // reset for next replay
    }
}

extern "C" void kernel_launch(void* const* d_in, const int* in_sizes, int n_in,
                              void* d_out, int out_size)
{
    const float* yt = (const float*)d_in[0];   // true_frames
    const float* yp = (const float*)d_in[1];   // predicted_frames
    spline_mse_r6<<<NBLK, NTHR>>>(yt, yp, (float*)d_out);
}

// round 7
// speedup vs baseline: 1.0337x; 1.0337x over previous
#include <cuda_runtime.h>

// SplineLoss on GB300: reference samples the spline only at integer knot
// times (t = 0,10,...,1020) where dx == 0.0 exactly, so all moment terms
// vanish: loss == mean over s,b,d of (true[b,10s,d]-pred[b,10s,d])^2.
//
// R7: spread the atomic tail. R6 had 824 u64 atomicAdds to ONE L2 address
// (serialized ~0.854 cy/op -> ~700cy exposed at end of kernel). Two-level:
//  - 8 bins on separate 256B lines, bin = blockIdx & 7 -> 103 ops/address,
//    parallel across LTS slices
//  - bin-last block (count==103) forwards exact bin total via one atomic
//    into a final accumulator; final count==8 -> write output
// All-integer fixed point (2^24): exact, commutative -> bit-deterministic.

#define T_ 1024
#define D4_ 16                   // 64 floats per row = 16 float4
#define S_ 103                   // sample times 0,10,...,1020
#define ROW_STRIDE4_ (T_ * D4_)  // float4 stride between batches
#define COUNT_ 843776.0          // 128 * 103 * 64
#define FIX_SCALE 16777216.0     // 2^24

constexpr int NBLK   = 8 * S_;   // 824 blocks, 8 per sample time
constexpr int NTHR   = 256;      // 16 batches x 16 float4
constexpr int NBINS  = 8;
constexpr int BINSZ  = NBLK / NBINS;   // 103

// each bin on its own 256B line (dodge L2 hash bit-7 pairing)
__device__ __align__(256) unsigned long long g_bins[NBINS * 32]; // use [i*32]
__device__ __align__(256) unsigned long long g_final = 0;

__global__ __launch_bounds__(NTHR) void spline_mse_r7(
    const float* __restrict__ yt, const float* __restrict__ yp,
    float* __restrict__ out)
{
    const int s = blockIdx.x >> 3;             // 0..102
    const int q = blockIdx.x & 7;              // batch group [16q, 16q+16)
    const int d4   = threadIdx.x & (D4_ - 1);
    const int brel = threadIdx.x >> 4;         // 0..15

    const int addr = s * 10 * D4_ + (q * 16 + brel) * ROW_STRIDE4_ + d4;
    const float4 va = __ldg((const float4*)yt + addr);
    const float4 vb = __ldg((const float4*)yp + addr);

    float e0 = va.x - vb.x;
    float e1 = va.y - vb.y;
    float e2 = va.z - vb.z;
    float e3 = va.w - vb.w;
    float acc = e0 * e0;
    acc = fmaf(e1, e1, acc);
    acc = fmaf(e2, e2, acc);
    acc = fmaf(e3, e3, acc);

    // block reduce (fixed order -> deterministic)
    #pragma unroll
    for (int o = 16; o > 0; o >>= 1)
        acc += __shfl_down_sync(0xffffffffu, acc, o);

    __shared__ float sh[NTHR / 32];
    if ((threadIdx.x & 31) == 0) sh[threadIdx.x >> 5] = acc;
    __syncthreads();

    if (threadIdx.x != 0) return;              // thread 0 only past here

    float v = sh[0];
    #pragma unroll
    for (int w = 1; w < NTHR / 32; w++) v += sh[w];

    // level 1: bin atomic (103 blocks per address, 8 addresses in parallel)
    unsigned long long fixed =
        __double2ull_rn((double)v * FIX_SCALE);          // v >= 0, exact int
    unsigned long long* bin = &g_bins[(blockIdx.x & (NBINS - 1)) * 32];
    unsigned long long old = atomicAdd(bin, (fixed << 16) | 1ull);

    if ((old & 0xFFFFull) != (unsigned long long)(BINSZ - 1)) return;

    // bin-last: forward exact bin total, reset bin for next replay
    unsigned long long bin_total = (old >> 16) + fixed;
    *bin = 0ull;                                         // no later readers
    unsigned long long fold = atomicAdd(&g_final, (bin_total << 16) | 1ull);

    if ((fold & 0xFFFFull) == (unsigned long long)(NBINS - 1)) {
        unsigned long long total = (fold >> 16) + bin_total;
        out[0] = (float)((double)total / (FIX_SCALE * COUNT_));
        g_final = 0ull;                                  // reset for replay
    }
}

extern "C" void kernel_launch(void* const* d_in, const int* in_sizes, int n_in,
                              void* d_out, int out_size)
{
    const float* yt = (const float*)d_in[0];   // true_frames
    const float* yp = (const float*)d_in[1];   // predicted_frames
    spline_mse_r7<<<NBLK, NTHR>>>(yt, yp, (float*)d_out);
}